// round 16
// baseline (speedup 1.0000x reference)
#include <cuda_runtime.h>
#include <cstdint>

#define S 128
#define C 32
#define NN 4096
#define T 512

extern __shared__ char dyn_smem[];

// ---------------- scratch ----------------
__device__ __align__(256) float g_wexp[T * C];    // exp(log_softmax(weights))
__device__ __align__(256) float g_pR[T * C * S];  // p_t, tf32-rounded [T*C, S]
__device__ __align__(256) float g_Pr[S * NN];     // emission probs, tf32-rounded [s][n]
__device__ __align__(256) float g_Tlvl[5][S * S]; // T^(4^k), tf32-rounded
__device__ __align__(256) float g_Tsq[S * S];     // squaring intermediate T^(2L)
__device__ unsigned g_bcount = 0;                 // grid-barrier counter (self-resetting)
__device__ volatile unsigned g_bsense = 0;        // grid-barrier sense (even flips/run)

// ---------------- helpers ----------------
__device__ __forceinline__ uint32_t smem_u32(const void* p) {
    uint32_t a;
    asm("{ .reg .u64 t; cvta.to.shared.u64 t, %1; cvt.u32.u64 %0, t; }" : "=r"(a) : "l"(p));
    return a;
}
__device__ __forceinline__ void cp_async16(uint32_t dst, const void* src) {
    asm volatile("cp.async.cg.shared.global [%0], [%1], 16;" :: "r"(dst), "l"(src));
}
#define CP_COMMIT() asm volatile("cp.async.commit_group;" ::: "memory")
#define CP_WAIT(n)  asm volatile("cp.async.wait_group %0;" :: "n"(n) : "memory")

__device__ __forceinline__ float to_tf32(float x) {
    uint32_t u;
    asm("cvt.rna.tf32.f32 %0, %1;" : "=r"(u) : "f"(x));
    return __uint_as_float(u);
}
__device__ __forceinline__ void mma_tf32(float* d, const uint32_t* a, const uint32_t* b) {
    asm volatile(
        "mma.sync.aligned.m16n8k8.row.col.f32.tf32.tf32.f32 "
        "{%0,%1,%2,%3},{%4,%5,%6,%7},{%8,%9},{%0,%1,%2,%3};"
        : "+f"(d[0]), "+f"(d[1]), "+f"(d[2]), "+f"(d[3])
        : "r"(a[0]), "r"(a[1]), "r"(a[2]), "r"(a[3]), "r"(b[0]), "r"(b[1]));
}
__device__ __forceinline__ float warpRedMax(float v) {
#pragma unroll
    for (int o = 16; o > 0; o >>= 1) v = fmaxf(v, __shfl_xor_sync(0xffffffffu, v, o));
    return v;
}
__device__ __forceinline__ float warpRedSum(float v) {
#pragma unroll
    for (int o = 16; o > 0; o >>= 1) v += __shfl_xor_sync(0xffffffffu, v, o);
    return v;
}

static constexpr int PW = 136;
static constexpr int MAT_W = 128 * PW;
static constexpr int EXP_GRID = 128;

static constexpr int A_PW = 132;
static constexpr int A_BYTES = 128 * A_PW * 4;     // 67584
static constexpr int B_NP = 136;
static constexpr int B_CHUNK = 64 * B_NP * 4;      // 34816
static constexpr int FUSED_SMEM = A_BYTES + 3 * B_CHUNK;  // 172032 (>= expand's 139264)

__device__ __forceinline__ void grid_barrier(unsigned& lsense, int tid) {
    __threadfence();
    __syncthreads();
    if (tid == 0) {
        unsigned ns = lsense ^ 1u;
        unsigned pre = atomicAdd(&g_bcount, 1u);
        if (pre == (unsigned)EXP_GRID - 1u) {
            atomicExch(&g_bcount, 0u);
            __threadfence();
            g_bsense = ns;
        } else {
            while (g_bsense != ns) { }
        }
    }
    __syncthreads();
    lsense ^= 1u;
}

// 16 rows [sqb*16,+16) of X*X (X smem pitch PW) -> gdst (row-major S, tf32)
__device__ __forceinline__ void square16(const float* X, float* gdst, int sqb,
                                         int wid, int lane) {
    int rbase = sqb * 16;
    float acc[2][4];
#pragma unroll
    for (int nt = 0; nt < 2; nt++)
#pragma unroll
        for (int e = 0; e < 4; e++) acc[nt][e] = 0.f;

#pragma unroll
    for (int kt = 0; kt < 16; kt++) {
        int r = rbase + (lane >> 2), k = kt * 8 + (lane & 3);
        uint32_t a[4];
        a[0] = __float_as_uint(X[r * PW + k]);
        a[1] = __float_as_uint(X[(r + 8) * PW + k]);
        a[2] = __float_as_uint(X[r * PW + k + 4]);
        a[3] = __float_as_uint(X[(r + 8) * PW + k + 4]);
#pragma unroll
        for (int nt = 0; nt < 2; nt++) {
            int n = wid * 16 + nt * 8 + (lane >> 2);
            uint32_t bf[2];
            bf[0] = __float_as_uint(X[k * PW + n]);
            bf[1] = __float_as_uint(X[(k + 4) * PW + n]);
            mma_tf32(acc[nt], a, bf);
        }
    }
    int r = rbase + (lane >> 2), c2 = (lane & 3) * 2;
#pragma unroll
    for (int nt = 0; nt < 2; nt++) {
        int col = wid * 16 + nt * 8 + c2;
        gdst[r * S + col]           = to_tf32(acc[nt][0]);
        gdst[r * S + col + 1]       = to_tf32(acc[nt][1]);
        gdst[(r + 8) * S + col]     = to_tf32(acc[nt][2]);
        gdst[(r + 8) * S + col + 1] = to_tf32(acc[nt][3]);
    }
}

// ================== THE single fused kernel ==================
__global__ __launch_bounds__(256, 1)
void fused_all(const float* __restrict__ init, const float* __restrict__ weights,
               const float* __restrict__ emis, const float* __restrict__ trans,
               float* __restrict__ o1, float* __restrict__ o2, float* __restrict__ o3,
               float* __restrict__ o4, float* __restrict__ o5) {
    char* sm = dyn_smem;
    uint32_t smb = smem_u32(sm);
    float* sm0 = reinterpret_cast<float*>(sm);
    int tid = threadIdx.x, lane = tid & 31, wid = tid >> 5;
    int bid = blockIdx.x;
    unsigned lsense = 0;

    // ================= phase 1: warp-tasked softmax =================
    if (wid == 0) {
        // emission row `bid` (4096 cols): o4 + g_Pr (tf32)
        const float4* src = reinterpret_cast<const float4*>(emis + (size_t)bid * NN);
        float m = -3.4e38f;
        for (int i = lane; i < NN / 4; i += 32) {
            float4 v = src[i];
            m = fmaxf(m, fmaxf(fmaxf(v.x, v.y), fmaxf(v.z, v.w)));
        }
        m = warpRedMax(m);
        float s = 0.f;
        for (int i = lane; i < NN / 4; i += 32) {
            float4 v = src[i];
            s += __expf(v.x - m) + __expf(v.y - m) + __expf(v.z - m) + __expf(v.w - m);
        }
        s = warpRedSum(s);
        float lse = m + __logf(s);
        float4* dlog = reinterpret_cast<float4*>(o4 + (size_t)bid * NN);
        float4* dpr = reinterpret_cast<float4*>(g_Pr + (size_t)bid * NN);
        for (int i = lane; i < NN / 4; i += 32) {
            float4 v = src[i];
            float4 l = make_float4(v.x - lse, v.y - lse, v.z - lse, v.w - lse);
            dlog[i] = l;
            dpr[i] = make_float4(to_tf32(__expf(l.x)), to_tf32(__expf(l.y)),
                                 to_tf32(__expf(l.z)), to_tf32(__expf(l.w)));
        }
    } else {
        int rowid = bid * 7 + (wid - 1);
        if (rowid < 512) {
            // weights row (32 cols): o5 + g_wexp
            float v = weights[(size_t)rowid * C + lane];
            float m = warpRedMax(v);
            float s = warpRedSum(__expf(v - m));
            float lse = m + __logf(s);
            float l = v - lse;
            o5[(size_t)rowid * C + lane] = l;
            g_wexp[(size_t)rowid * C + lane] = __expf(l);
        } else if (rowid < 672) {
            // 128-col rows: init (o3 t=0 + g_pR) or trans (g_Tlvl[0])
            int r = rowid - 512;
            const float* src;
            float* dlog = nullptr;
            float* dexp;
            if (r < 32) {
                src = init + (size_t)r * S;
                dlog = o3 + (size_t)r * S;
                dexp = g_pR + (size_t)r * S;
            } else {
                src = trans + (size_t)(r - 32) * S;
                dexp = g_Tlvl[0] + (size_t)(r - 32) * S;
            }
            float v0 = src[lane], v1 = src[lane + 32], v2 = src[lane + 64], v3 = src[lane + 96];
            float m = warpRedMax(fmaxf(fmaxf(v0, v1), fmaxf(v2, v3)));
            float s = warpRedSum(__expf(v0 - m) + __expf(v1 - m) + __expf(v2 - m) + __expf(v3 - m));
            float lse = m + __logf(s);
            v0 -= lse; v1 -= lse; v2 -= lse; v3 -= lse;
            if (dlog) {
                dlog[lane] = v0; dlog[lane + 32] = v1;
                dlog[lane + 64] = v2; dlog[lane + 96] = v3;
            }
            dexp[lane]      = to_tf32(__expf(v0));
            dexp[lane + 32] = to_tf32(__expf(v1));
            dexp[lane + 64] = to_tf32(__expf(v2));
            dexp[lane + 96] = to_tf32(__expf(v3));
        }
    }
    grid_barrier(lsense, tid);   // flip 1

    // ================= phase 2: radix-4 doubling (5 levels) =================
    {
        float* Ts = sm0;
        float* W2 = sm0 + MAT_W;
#pragma unroll 1
        for (int lvl = 0; lvl < 5; lvl++) {
            int L = 1 << (2 * lvl);
            const float4* gT = reinterpret_cast<const float4*>(g_Tlvl[lvl]);
            for (int i = tid; i < 4096; i += 256) {
                int row = i >> 5, c = i & 31;
                *reinterpret_cast<float4*>(Ts + row * PW + c * 4) = gT[i];
            }
            __syncthreads();

            int nP = min(3 * L, 512 - L);
#pragma unroll 1
            for (int task = bid; task < nP; task += EXP_GRID) {
                float* X0 = W2;
                float* X1 = W2 + 32 * PW;
                int t = L + task;
                int m = t / L;
                int j = t - m * L;

                const float4* gp = reinterpret_cast<const float4*>(g_pR + (size_t)j * C * S);
                for (int i = tid; i < 1024; i += 256) {
                    int row = i >> 5, c = i & 31;
                    *reinterpret_cast<float4*>(X0 + row * PW + c * 4) = gp[i];
                }
                __syncthreads();

                int wm = wid & 1, wn = wid >> 1;
                float* srcp = X0;
                float* dstp = X1;
#pragma unroll 1
                for (int it = 0; it < m; it++) {
                    float acc[4][4];
#pragma unroll
                    for (int nt = 0; nt < 4; nt++)
#pragma unroll
                        for (int e = 0; e < 4; e++) acc[nt][e] = 0.f;

#pragma unroll
                    for (int kt = 0; kt < 16; kt++) {
                        int r = wm * 16 + (lane >> 2), k = kt * 8 + (lane & 3);
                        uint32_t a[4];
                        a[0] = __float_as_uint(srcp[r * PW + k]);
                        a[1] = __float_as_uint(srcp[(r + 8) * PW + k]);
                        a[2] = __float_as_uint(srcp[r * PW + k + 4]);
                        a[3] = __float_as_uint(srcp[(r + 8) * PW + k + 4]);
#pragma unroll
                        for (int nt = 0; nt < 4; nt++) {
                            int n = wn * 32 + nt * 8 + (lane >> 2);
                            uint32_t bf[2];
                            bf[0] = __float_as_uint(Ts[k * PW + n]);
                            bf[1] = __float_as_uint(Ts[(k + 4) * PW + n]);
                            mma_tf32(acc[nt], a, bf);
                        }
                    }
                    int r = wm * 16 + (lane >> 2), c2 = (lane & 3) * 2;
#pragma unroll
                    for (int nt = 0; nt < 4; nt++) {
                        int col = wn * 32 + nt * 8 + c2;
                        dstp[r * PW + col]           = to_tf32(acc[nt][0]);
                        dstp[r * PW + col + 1]       = to_tf32(acc[nt][1]);
                        dstp[(r + 8) * PW + col]     = to_tf32(acc[nt][2]);
                        dstp[(r + 8) * PW + col + 1] = to_tf32(acc[nt][3]);
                    }
                    __syncthreads();
                    float* tmp = srcp; srcp = dstp; dstp = tmp;
                }

                float4* gout = reinterpret_cast<float4*>(g_pR + (size_t)t * C * S);
                float* o3out = o3 + (size_t)t * C * S;
                for (int i = tid; i < 1024; i += 256) {
                    int row = i >> 5, c = i & 31;
                    float4 v = *reinterpret_cast<float4*>(srcp + row * PW + c * 4);
                    gout[i] = v;
                    int idx = row * S + c * 4;
                    o3out[idx]     = __logf(v.x);
                    o3out[idx + 1] = __logf(v.y);
                    o3out[idx + 2] = __logf(v.z);
                    o3out[idx + 3] = __logf(v.w);
                }
                __syncthreads();
            }

            if (lvl < 4) {
                if (bid >= EXP_GRID - 8) {
                    square16(Ts, g_Tsq, bid - (EXP_GRID - 8), wid, lane);
                }
                grid_barrier(lsense, tid);   // flips 2,4,6,8
                if (bid >= EXP_GRID - 8) {
                    const float4* gS = reinterpret_cast<const float4*>(g_Tsq);
                    for (int i = tid; i < 4096; i += 256) {
                        int row = i >> 5, c = i & 31;
                        *reinterpret_cast<float4*>(W2 + row * PW + c * 4) = gS[i];
                    }
                    __syncthreads();
                    square16(W2, g_Tlvl[lvl + 1], bid - (EXP_GRID - 8), wid, lane);
                }
                grid_barrier(lsense, tid);   // flips 3,5,7,9
            }
        }
    }
    grid_barrier(lsense, tid);   // flip 10 (sense back to 0)

    // ================= phase 3: GEMM + log epilogue (quad = bid) =================
    {
        int quad = bid;
        const uint4* srcA = reinterpret_cast<const uint4*>(g_pR) + (size_t)quad * 128 * 32;
#pragma unroll
        for (int j = 0; j < 16; j++) {
            int i = tid + j * 256;
            int row = i >> 5, c = i & 31;
            cp_async16(smb + row * (A_PW * 4) + c * 16, srcA + row * 32 + c);
        }
        CP_COMMIT();

        auto issueB = [&](int chunk) {
            int tile = chunk >> 1, half = chunk & 1;
            uint32_t base = smb + A_BYTES + (chunk % 3) * B_CHUNK;
#pragma unroll
            for (int j = 0; j < 8; j++) {
                int i = tid + j * 256;
                int k = i >> 5, c = i & 31;
                const uint4* src = reinterpret_cast<const uint4*>(g_Pr)
                                   + (size_t)(half * 64 + k) * (NN / 4) + tile * 32 + c;
                cp_async16(base + k * (B_NP * 4) + c * 16, src);
            }
        };
        issueB(0); CP_COMMIT();
        issueB(1); CP_COMMIT();
        issueB(2); CP_COMMIT();

        int mrow = (wid & 3) * 32 + (lane >> 2);
        int nrowBase = (wid >> 2) * 64 + (lane >> 2);
        int kt = lane & 3;
        int t = quad * 4 + (wid & 3);
        int r0 = lane >> 2, cq = lane & 3;
        float wlane = g_wexp[t * C + lane];
        float wr0  = __shfl_sync(0xffffffffu, wlane, r0);
        float wr0b = __shfl_sync(0xffffffffu, wlane, r0 + 8);
        float wr1  = __shfl_sync(0xffffffffu, wlane, 16 + r0);
        float wr1b = __shfl_sync(0xffffffffu, wlane, 16 + r0 + 8);

        const uint32_t* As = reinterpret_cast<const uint32_t*>(sm);
        float acc[2][8][4];

        for (int chunk = 0; chunk < 64; chunk++) {
            int tile = chunk >> 1, half = chunk & 1;
            CP_WAIT(2);
            __syncthreads();
            const uint32_t* Bs =
                reinterpret_cast<const uint32_t*>(sm + A_BYTES + (chunk % 3) * B_CHUNK);

            if (half == 0) {
#pragma unroll
                for (int mt = 0; mt < 2; mt++)
#pragma unroll
                    for (int nt = 0; nt < 8; nt++)
#pragma unroll
                        for (int e = 0; e < 4; e++) acc[mt][nt][e] = 0.f;
            }

#pragma unroll
            for (int step = 0; step < 8; step++) {
                int lk = step * 8 + kt;
                int k0 = half * 64 + lk;
                uint32_t a[2][4];
#pragma unroll
                for (int mt = 0; mt < 2; mt++) {
                    int r = mrow + mt * 16;
                    a[mt][0] = As[r * A_PW + k0];
                    a[mt][1] = As[(r + 8) * A_PW + k0];
                    a[mt][2] = As[r * A_PW + k0 + 4];
                    a[mt][3] = As[(r + 8) * A_PW + k0 + 4];
                }
#pragma unroll
                for (int nt = 0; nt < 8; nt++) {
                    int n = nrowBase + nt * 8;
                    uint32_t bf[2];
                    bf[0] = Bs[lk * B_NP + n];
                    bf[1] = Bs[(lk + 4) * B_NP + n];
#pragma unroll
                    for (int mt = 0; mt < 2; mt++) mma_tf32(acc[mt][nt], a[mt], bf);
                }
            }
            __syncthreads();
            if (chunk + 3 < 64) issueB(chunk + 3);
            CP_COMMIT();

            if (half == 1) {
                int nb = tile * 128;
                int nbL = (wid >> 2) * 64;
#pragma unroll
                for (int nt = 0; nt < 8; nt++) {
                    int ncol = nb + nbL + nt * 8 + cq * 2;
                    float v0, v1;
                    {
                        float2 s0 = make_float2(__logf(acc[0][nt][0]), __logf(acc[0][nt][1]));
                        float2 s1 = make_float2(__logf(acc[0][nt][2]), __logf(acc[0][nt][3]));
                        *reinterpret_cast<float2*>(&o2[((size_t)(t * C + r0)) * NN + ncol]) = s0;
                        *reinterpret_cast<float2*>(&o2[((size_t)(t * C + r0 + 8)) * NN + ncol]) = s1;
                        v0 = acc[0][nt][0] * wr0 + acc[0][nt][2] * wr0b;
                        v1 = acc[0][nt][1] * wr0 + acc[0][nt][3] * wr0b;
                    }
                    {
                        float2 s0 = make_float2(__logf(acc[1][nt][0]), __logf(acc[1][nt][1]));
                        float2 s1 = make_float2(__logf(acc[1][nt][2]), __logf(acc[1][nt][3]));
                        *reinterpret_cast<float2*>(&o2[((size_t)(t * C + 16 + r0)) * NN + ncol]) = s0;
                        *reinterpret_cast<float2*>(&o2[((size_t)(t * C + 24 + r0)) * NN + ncol]) = s1;
                        v0 += acc[1][nt][0] * wr1 + acc[1][nt][2] * wr1b;
                        v1 += acc[1][nt][1] * wr1 + acc[1][nt][3] * wr1b;
                    }
#pragma unroll
                    for (int o = 4; o < 32; o <<= 1) {
                        v0 += __shfl_xor_sync(0xffffffffu, v0, o);
                        v1 += __shfl_xor_sync(0xffffffffu, v1, o);
                    }
                    if (lane < 4) {
                        int n = nb + nbL + nt * 8 + lane * 2;
                        *reinterpret_cast<float2*>(&o1[(size_t)t * NN + n]) =
                            make_float2(__logf(v0), __logf(v1));
                    }
                }
            }
        }
    }
}

// ---------------- launch ----------------
extern "C" void kernel_launch(void* const* d_in, const int* in_sizes, int n_in,
                              void* d_out, int out_size) {
    (void)in_sizes; (void)n_in; (void)out_size;
    const float* init    = (const float*)d_in[0];   // [32,128]
    const float* weights = (const float*)d_in[1];   // [512,32]
    const float* emis    = (const float*)d_in[2];   // [128,4096]
    const float* trans   = (const float*)d_in[3];   // [128,128]

    float* out = (float*)d_out;
    float* o1 = out;                       // [512,4096]
    float* o2 = o1 + (size_t)T * NN;       // [512,32,4096]
    float* o3 = o2 + (size_t)T * C * NN;   // [512,32,128]
    float* o4 = o3 + (size_t)T * C * S;    // [128,4096]
    float* o5 = o4 + (size_t)S * NN;       // [512,32]

    cudaFuncSetAttribute(fused_all, cudaFuncAttributeMaxDynamicSharedMemorySize, FUSED_SMEM);

    // everything in ONE persistent kernel (10 internal grid barriers, even count)
    fused_all<<<EXP_GRID, 256, FUSED_SMEM>>>(init, weights, emis, trans, o1, o2, o3, o4, o5);
}